// round 15
// baseline (speedup 1.0000x reference)
#include <cuda_runtime.h>
#include <cuda_bf16.h>

#define BB   16
#define CC   192
#define TXN  1024
#define MAXY 4096

// Scratch: token index per output frame (-1 = no token -> z = noise)
__device__ int g_idx[BB * MAXY];

// One block per batch, 1024 threads.
// PDL trigger fires AFTER g_idx is fully written (y_mask, which expand never
// reads, is written after the trigger).
__global__ void build_map_kernel(const float* __restrict__ logw,
                                 const int* __restrict__ x_lengths,
                                 float* __restrict__ y_mask_out) {
    __shared__ int warp_sums[32];
    const int b    = blockIdx.x;
    const int t    = threadIdx.x;
    const int lane = t & 31;
    const int wid  = t >> 5;

    const int xlen = max(x_lengths[b], 1);
    int w = 0;
    if (t < xlen) {
        // accurate expf: feeds ceil(), ulp flips at integer boundaries matter
        w = (int)ceilf(expf(logw[b * TXN + t]));
    }

    // warp-level inclusive scan
    int c = w;
    #pragma unroll
    for (int o = 1; o < 32; o <<= 1) {
        int v = __shfl_up_sync(0xffffffffu, c, o);
        if (lane >= o) c += v;
    }
    if (lane == 31) warp_sums[wid] = c;
    __syncthreads();
    if (wid == 0) {
        int v = warp_sums[lane];
        #pragma unroll
        for (int o = 1; o < 32; o <<= 1) {
            int u = __shfl_up_sync(0xffffffffu, v, o);
            if (lane >= o) v += u;
        }
        warp_sums[lane] = v;
    }
    __syncthreads();

    const int base  = (wid > 0) ? warp_sums[wid - 1] : 0;
    const int cum   = base + c;               // inclusive prefix sum
    const int total = warp_sums[31];
    const int ylen  = min(max(total, 1), MAXY);

    int* __restrict__ row = g_idx + b * MAXY;

    // band scatter: frames [cum-w, cum) belong to token t
    const int end = min(cum, MAXY);
    for (int ty = cum - w; ty < end; ty++) row[ty] = t;

    // tail fill: frames beyond total have no token
    const int tail0 = min(total, MAXY);
    for (int ty = tail0 + t; ty < MAXY; ty += TXN) row[ty] = -1;

    // g_idx complete for this block -> release to dependent kernel
    __syncthreads();
#if __CUDA_ARCH__ >= 900
    cudaTriggerProgrammaticLaunchCompletion();
#endif

    // y_mask, one float4 per thread (not read by expand)
    if (y_mask_out != nullptr) {
        const int v0 = t * 4;
        float4 m;
        m.x = (v0 + 0 < ylen) ? 1.0f : 0.0f;
        m.y = (v0 + 1 < ylen) ? 1.0f : 0.0f;
        m.z = (v0 + 2 < ylen) ? 1.0f : 0.0f;
        m.w = (v0 + 3 < ylen) ? 1.0f : 0.0f;
        reinterpret_cast<float4*>(y_mask_out + b * MAXY)[t] = m;
    }
}

// EXACT R8 schedule with ONE change: noise uses a DEFAULT-cached load
// (was __ldcs). noise is re-read on every graph replay, so L2 residency pays
// each iteration; z keeps __stcs (evict-first) so its dirty lines don't
// evict the noise working set (R13 proved removing the store hint costs
// ~8us/replay). Resident set noise+m/s+idx ~75MB < 126MB L2.
__global__ void __launch_bounds__(256)
expand_kernel(const float* __restrict__ m_p,
              const float* __restrict__ logs_p,
              const float* __restrict__ noise,
              float* __restrict__ z) {
    __shared__ float sm[TXN];
    __shared__ float ss[TXN];

    const int bc  = blockIdx.x;      // 0..BB*CC-1
    const int b   = bc / CC;
    const int tid = threadIdx.x;

    const float4* __restrict__ nz4 = reinterpret_cast<const float4*>(noise) + (size_t)bc * (MAXY / 4);
    float4*       __restrict__ z4  = reinterpret_cast<float4*>(z)           + (size_t)bc * (MAXY / 4);
    const int4*   __restrict__ ix4 = reinterpret_cast<const int4*>(g_idx)   + b * (MAXY / 4);
    const float4* __restrict__ m4  = reinterpret_cast<const float4*>(m_p    + (size_t)bc * TXN);
    const float4* __restrict__ s4  = reinterpret_cast<const float4*>(logs_p + (size_t)bc * TXN);

    // ---- independent loads: overlap build_map under PDL ----
    float4 mv = m4[tid];
    float4 sv = s4[tid];

    float4 n[4];
    #pragma unroll
    for (int j = 0; j < 4; j++) n[j] = nz4[tid + j * 256];   // default cache: L2-resident across replays

    // ---- wait for g_idx, then the dependent loads ----
#if __CUDA_ARCH__ >= 900
    cudaGridDependencySynchronize();
#endif
    int4 ix[4];
    #pragma unroll
    for (int j = 0; j < 4; j++) ix[j] = ix4[tid + j * 256];

    reinterpret_cast<float4*>(sm)[tid] = mv;
    reinterpret_cast<float4*>(ss)[tid] = sv;
    __syncthreads();

    // ---- compute: LDS gathers (broadcast-friendly), MUFU exp, FMA ----
    #pragma unroll
    for (int j = 0; j < 4; j++) {
        const int   tt[4] = {ix[j].x, ix[j].y, ix[j].z, ix[j].w};
        const float nv[4] = {n[j].x, n[j].y, n[j].z, n[j].w};
        float ov[4];
        #pragma unroll
        for (int k = 0; k < 4; k++) {
            const int t = tt[k];
            ov[k] = (t >= 0) ? fmaf(nv[k], __expf(ss[t]), sm[t]) : nv[k];
        }
        __stcs(&z4[tid + j * 256], make_float4(ov[0], ov[1], ov[2], ov[3]));
    }
}

extern "C" void kernel_launch(void* const* d_in, const int* in_sizes, int n_in,
                              void* d_out, int out_size) {
    const float* m_p    = (const float*)d_in[0];
    const float* logs_p = (const float*)d_in[1];
    const float* logw   = (const float*)d_in[2];
    const float* noise  = (const float*)d_in[3];
    const int*   xlens  = (const int*)d_in[4];

    float* out = (float*)d_out;
    const int zsize = BB * CC * MAXY;            // 12,582,912
    float* z = out;
    float* y_mask = (out_size >= zsize + BB * MAXY) ? (out + zsize) : nullptr;

    build_map_kernel<<<BB, TXN>>>(logw, xlens, y_mask);

    // expand with programmatic dependent launch: independent loads overlap
    // build_map; cudaGridDependencySynchronize() guards the g_idx reads.
    cudaLaunchConfig_t cfg = {};
    cfg.gridDim  = dim3(BB * CC);
    cfg.blockDim = dim3(256);
    cfg.dynamicSmemBytes = 0;
    cfg.stream = 0;
    cudaLaunchAttribute attr[1];
    attr[0].id = cudaLaunchAttributeProgrammaticStreamSerialization;
    attr[0].val.programmaticStreamSerializationAllowed = 1;
    cfg.attrs = attr;
    cfg.numAttrs = 1;
    cudaLaunchKernelEx(&cfg, expand_kernel, m_p, logs_p, noise, z);
}

// round 16
// speedup vs baseline: 1.2318x; 1.2318x over previous
#include <cuda_runtime.h>
#include <cuda_bf16.h>

#define BB   16
#define CC   192
#define TXN  1024
#define MAXY 4096

// Scratch: token index per output frame (-1 = no token -> z = noise)
__device__ int g_idx[BB * MAXY];

// One block per batch, 1024 threads.
// PDL trigger fires AFTER g_idx is fully written (y_mask, which expand never
// reads, is written after the trigger).
__global__ void build_map_kernel(const float* __restrict__ logw,
                                 const int* __restrict__ x_lengths,
                                 float* __restrict__ y_mask_out) {
    __shared__ int warp_sums[32];
    const int b    = blockIdx.x;
    const int t    = threadIdx.x;
    const int lane = t & 31;
    const int wid  = t >> 5;

    const int xlen = max(x_lengths[b], 1);
    int w = 0;
    if (t < xlen) {
        // accurate expf: feeds ceil(), ulp flips at integer boundaries matter
        w = (int)ceilf(expf(logw[b * TXN + t]));
    }

    // warp-level inclusive scan
    int c = w;
    #pragma unroll
    for (int o = 1; o < 32; o <<= 1) {
        int v = __shfl_up_sync(0xffffffffu, c, o);
        if (lane >= o) c += v;
    }
    if (lane == 31) warp_sums[wid] = c;
    __syncthreads();
    if (wid == 0) {
        int v = warp_sums[lane];
        #pragma unroll
        for (int o = 1; o < 32; o <<= 1) {
            int u = __shfl_up_sync(0xffffffffu, v, o);
            if (lane >= o) v += u;
        }
        warp_sums[lane] = v;
    }
    __syncthreads();

    const int base  = (wid > 0) ? warp_sums[wid - 1] : 0;
    const int cum   = base + c;               // inclusive prefix sum
    const int total = warp_sums[31];
    const int ylen  = min(max(total, 1), MAXY);

    int* __restrict__ row = g_idx + b * MAXY;

    // band scatter: frames [cum-w, cum) belong to token t
    const int end = min(cum, MAXY);
    for (int ty = cum - w; ty < end; ty++) row[ty] = t;

    // tail fill: frames beyond total have no token
    const int tail0 = min(total, MAXY);
    for (int ty = tail0 + t; ty < MAXY; ty += TXN) row[ty] = -1;

    // g_idx complete for this block -> release to dependent kernel
    __syncthreads();
#if __CUDA_ARCH__ >= 900
    cudaTriggerProgrammaticLaunchCompletion();
#endif

    // y_mask, one float4 per thread (not read by expand)
    if (y_mask_out != nullptr) {
        const int v0 = t * 4;
        float4 m;
        m.x = (v0 + 0 < ylen) ? 1.0f : 0.0f;
        m.y = (v0 + 1 < ylen) ? 1.0f : 0.0f;
        m.z = (v0 + 2 < ylen) ? 1.0f : 0.0f;
        m.w = (v0 + 3 < ylen) ? 1.0f : 0.0f;
        reinterpret_cast<float4*>(y_mask_out + b * MAXY)[t] = m;
    }
}

// Best measured configuration (R8, 18.91us; independently confirmed by R11):
// one block per (b,c) row, 256 threads, 4x float4 per thread.
// - All global loads issue before the single barrier (no per-block LDG bubble)
// - m/logs rows staged in smem; gathers are broadcast-friendly LDS
// - __ldcs on noise + __stcs on z: evict-first on both 50MB streams is
//   jointly optimal (measured matrix R8/R13/R14/R15) — retaining either
//   in L2 poisons graph-replay steady state
// - PDL: independent loads overlap build_map; only g_idx reads wait
__global__ void __launch_bounds__(256)
expand_kernel(const float* __restrict__ m_p,
              const float* __restrict__ logs_p,
              const float* __restrict__ noise,
              float* __restrict__ z) {
    __shared__ float sm[TXN];
    __shared__ float ss[TXN];

    const int bc  = blockIdx.x;      // 0..BB*CC-1
    const int b   = bc / CC;
    const int tid = threadIdx.x;

    const float4* __restrict__ nz4 = reinterpret_cast<const float4*>(noise) + (size_t)bc * (MAXY / 4);
    float4*       __restrict__ z4  = reinterpret_cast<float4*>(z)           + (size_t)bc * (MAXY / 4);
    const int4*   __restrict__ ix4 = reinterpret_cast<const int4*>(g_idx)   + b * (MAXY / 4);
    const float4* __restrict__ m4  = reinterpret_cast<const float4*>(m_p    + (size_t)bc * TXN);
    const float4* __restrict__ s4  = reinterpret_cast<const float4*>(logs_p + (size_t)bc * TXN);

    // ---- independent loads: overlap build_map under PDL ----
    float4 mv = m4[tid];
    float4 sv = s4[tid];

    float4 n[4];
    #pragma unroll
    for (int j = 0; j < 4; j++) n[j] = __ldcs(&nz4[tid + j * 256]);

    // ---- wait for g_idx, then the dependent loads ----
#if __CUDA_ARCH__ >= 900
    cudaGridDependencySynchronize();
#endif
    int4 ix[4];
    #pragma unroll
    for (int j = 0; j < 4; j++) ix[j] = ix4[tid + j * 256];

    reinterpret_cast<float4*>(sm)[tid] = mv;
    reinterpret_cast<float4*>(ss)[tid] = sv;
    __syncthreads();

    // ---- compute: LDS gathers (broadcast-friendly), MUFU exp, FMA ----
    #pragma unroll
    for (int j = 0; j < 4; j++) {
        const int   tt[4] = {ix[j].x, ix[j].y, ix[j].z, ix[j].w};
        const float nv[4] = {n[j].x, n[j].y, n[j].z, n[j].w};
        float ov[4];
        #pragma unroll
        for (int k = 0; k < 4; k++) {
            const int t = tt[k];
            ov[k] = (t >= 0) ? fmaf(nv[k], __expf(ss[t]), sm[t]) : nv[k];
        }
        __stcs(&z4[tid + j * 256], make_float4(ov[0], ov[1], ov[2], ov[3]));
    }
}

extern "C" void kernel_launch(void* const* d_in, const int* in_sizes, int n_in,
                              void* d_out, int out_size) {
    const float* m_p    = (const float*)d_in[0];
    const float* logs_p = (const float*)d_in[1];
    const float* logw   = (const float*)d_in[2];
    const float* noise  = (const float*)d_in[3];
    const int*   xlens  = (const int*)d_in[4];

    float* out = (float*)d_out;
    const int zsize = BB * CC * MAXY;            // 12,582,912
    float* z = out;
    float* y_mask = (out_size >= zsize + BB * MAXY) ? (out + zsize) : nullptr;

    build_map_kernel<<<BB, TXN>>>(logw, xlens, y_mask);

    // expand with programmatic dependent launch: independent loads overlap
    // build_map; cudaGridDependencySynchronize() guards the g_idx reads.
    cudaLaunchConfig_t cfg = {};
    cfg.gridDim  = dim3(BB * CC);
    cfg.blockDim = dim3(256);
    cfg.dynamicSmemBytes = 0;
    cfg.stream = 0;
    cudaLaunchAttribute attr[1];
    attr[0].id = cudaLaunchAttributeProgrammaticStreamSerialization;
    attr[0].val.programmaticStreamSerializationAllowed = 1;
    cfg.attrs = attr;
    cfg.numAttrs = 1;
    cudaLaunchKernelEx(&cfg, expand_kernel, m_p, logs_p, noise, z);
}